// round 1
// baseline (speedup 1.0000x reference)
#include <cuda_runtime.h>

#define T_STEPS 512
#define BATCH   512
#define SDIM    64
#define HID     128
#define ADIM    10

#define NCTA    128
#define NTHR    256
#define HS_SPLIT 8     // hidden slices (16 hidden each)
#define HPC     16     // hidden per CTA
#define BPC     32     // batch per CTA
#define KA      192    // layer0 K = 64 (x) + 128 (h)
#define KB      256    // layer1 K = 128 (h0) + 128 (h1)

#define SWA_FLOATS (4*HPC*KA)   // 12288
#define SWB_FLOATS (4*HPC*KB)   // 16384
#define SIN_FLOATS (KB*33)      // 8448  (staging, transposed [k][b], pad 33)
#define SMEM_BYTES ((SWA_FLOATS + SWB_FLOATS + SIN_FLOATS) * 4)  // 148480

// Global scratch (ping-pong hidden state, stored transposed [j][b_global])
__device__ float g_h0[2][HID * BATCH];
__device__ float g_h1[2][HID * BATCH];

// Two-slot self-cleaning grid barrier state (zero-init; scheme keeps it clean
// across graph replays as long as total barrier count per launch is EVEN).
__device__ int          g_cnt[2];
__device__ volatile int g_flag[2];

__device__ __forceinline__ float tanh_fast(float x) {
    float r; asm("tanh.approx.f32 %0, %1;" : "=f"(r) : "f"(x)); return r;
}
__device__ __forceinline__ float sigmoid_fast(float x) {
    return 0.5f * tanh_fast(0.5f * x) + 0.5f;
}

__device__ __forceinline__ void grid_barrier(int slot) {
    __syncthreads();
    if (threadIdx.x == 0) {
        __threadfence();
        int old = atomicAdd(&g_cnt[slot], 1);
        if (old == NCTA - 1) {
            // All arrived. Reset the OTHER slot (everyone has passed it),
            // then release this one.
            g_cnt[slot ^ 1]  = 0;
            g_flag[slot ^ 1] = 0;
            __threadfence();
            g_flag[slot] = 1;
        } else {
            while (g_flag[slot] == 0) { __nanosleep(32); }
            __threadfence();
        }
    }
    __syncthreads();
}

__global__ void __launch_bounds__(NTHR, 1)
lstm_persistent(const float* __restrict__ x,
                const float* __restrict__ W_ih0, const float* __restrict__ W_hh0,
                const float* __restrict__ b_ih0, const float* __restrict__ b_hh0,
                const float* __restrict__ W_ih1, const float* __restrict__ W_hh1,
                const float* __restrict__ b_ih1, const float* __restrict__ b_hh1,
                const float* __restrict__ W_out, const float* __restrict__ b_out,
                float* __restrict__ out)
{
    extern __shared__ float smem[];
    float* sWA = smem;                       // [4][HPC][KA] k-contiguous
    float* sWB = sWA + SWA_FLOATS;           // [4][HPC][KB]
    float* sIn = sWB + SWB_FLOATS;           // [k][b] stride 33

    const int tid  = threadIdx.x;
    const int bid  = blockIdx.x;
    const int hs   = bid & (HS_SPLIT - 1);   // hidden slice 0..7
    const int bs   = bid >> 3;               // batch slice 0..15
    const int j0   = hs * HPC;               // first hidden of slice
    const int b0   = bs * BPC;               // first batch of slice
    const int b    = tid & 31;               // lane batch 0..31
    const int jgrp = tid >> 5;               // warp id 0..7 -> 2 hidden units
    const int jl0  = jgrp * 2;               // local hidden (even of pair)

    // ---- Load weight slices into smem (once) ----
    for (int idx = tid; idx < SWA_FLOATS; idx += NTHR) {
        int g  = idx / (HPC * KA);
        int r  = idx - g * (HPC * KA);
        int jl = r / KA;
        int k  = r - jl * KA;
        int row = g * HID + j0 + jl;
        sWA[idx] = (k < SDIM) ? W_ih0[row * SDIM + k]
                              : W_hh0[row * HID + (k - SDIM)];
    }
    for (int idx = tid; idx < SWB_FLOATS; idx += NTHR) {
        int g  = idx / (HPC * KB);
        int r  = idx - g * (HPC * KB);
        int jl = r / KB;
        int k  = r - jl * KB;
        int row = g * HID + j0 + jl;
        sWB[idx] = (k < HID) ? W_ih1[row * HID + k]
                             : W_hh1[row * HID + (k - HID)];
    }

    // ---- Per-thread biases (combined b_ih + b_hh) ----
    float bA0[4], bA1[4], bB0[4], bB1[4];
    {
        int jg = j0 + jl0;
        #pragma unroll
        for (int g = 0; g < 4; ++g) {
            bA0[g] = b_ih0[g * HID + jg]     + b_hh0[g * HID + jg];
            bA1[g] = b_ih0[g * HID + jg + 1] + b_hh0[g * HID + jg + 1];
            bB0[g] = b_ih1[g * HID + jg]     + b_hh1[g * HID + jg];
            bB1[g] = b_ih1[g * HID + jg + 1] + b_hh1[g * HID + jg + 1];
        }
    }

    // ---- Zero initial state buffers (p = 0) ----
    {
        int gid = bid * NTHR + tid;
        for (int i = gid; i < HID * BATCH; i += NCTA * NTHR) {
            g_h0[0][i] = 0.0f;
            g_h1[0][i] = 0.0f;
        }
    }

    int bar = 0;
    grid_barrier(bar & 1); ++bar;            // barrier #0 (state zeroed, smem done)

    float c0a = 0.f, c0b = 0.f, c1a = 0.f, c1b = 0.f;
    int p = 0;

    for (int t = 0; t < T_STEPS; ++t) {
        // ================= Phase A: layer 0 =================
        // Stage x_t part (k in [0,64)) — lanes sweep k for coalesced x reads
        for (int idx = tid; idx < SDIM * BPC; idx += NTHR) {
            int k  = idx & (SDIM - 1);
            int bb = idx >> 6;
            sIn[k * 33 + bb] = x[(((size_t)t * BATCH) + b0 + bb) * SDIM + k];
        }
        // Stage h0 part (k in [64,192)) — lanes sweep batch (g_h0 is [j][b])
        for (int idx = tid; idx < HID * BPC; idx += NTHR) {
            int bb = idx & 31;
            int k  = idx >> 5;
            sIn[(SDIM + k) * 33 + bb] = g_h0[p][k * BATCH + b0 + bb];
        }
        __syncthreads();

        {
            float a0[4], a1[4];
            #pragma unroll
            for (int g = 0; g < 4; ++g) { a0[g] = bA0[g]; a1[g] = bA1[g]; }

            #pragma unroll 2
            for (int k4 = 0; k4 < KA; k4 += 4) {
                float x0 = sIn[(k4 + 0) * 33 + b];
                float x1 = sIn[(k4 + 1) * 33 + b];
                float x2 = sIn[(k4 + 2) * 33 + b];
                float x3 = sIn[(k4 + 3) * 33 + b];
                #pragma unroll
                for (int g = 0; g < 4; ++g) {
                    float4 w0 = *(const float4*)&sWA[(g * HPC + jl0) * KA + k4];
                    a0[g] = fmaf(w0.x, x0, fmaf(w0.y, x1, fmaf(w0.z, x2, fmaf(w0.w, x3, a0[g]))));
                    float4 w1 = *(const float4*)&sWA[(g * HPC + jl0 + 1) * KA + k4];
                    a1[g] = fmaf(w1.x, x0, fmaf(w1.y, x1, fmaf(w1.z, x2, fmaf(w1.w, x3, a1[g]))));
                }
            }
            // cell update (gate order i,f,g,o)
            {
                float iG = sigmoid_fast(a0[0]), fG = sigmoid_fast(a0[1]);
                float gG = tanh_fast(a0[2]),    oG = sigmoid_fast(a0[3]);
                c0a = fG * c0a + iG * gG;
                g_h0[p ^ 1][(j0 + jl0) * BATCH + b0 + b] = oG * tanh_fast(c0a);
            }
            {
                float iG = sigmoid_fast(a1[0]), fG = sigmoid_fast(a1[1]);
                float gG = tanh_fast(a1[2]),    oG = sigmoid_fast(a1[3]);
                c0b = fG * c0b + iG * gG;
                g_h0[p ^ 1][(j0 + jl0 + 1) * BATCH + b0 + b] = oG * tanh_fast(c0b);
            }
        }

        // Output head for step t-1 (h1(t-1) complete in g_h1[p] after barrier B)
        if (t > 0 && tid < 4 * ADIM) {
            int lb = tid / ADIM;
            int a  = tid - lb * ADIM;
            int bg = b0 + hs * 4 + lb;
            float s = b_out[a];
            #pragma unroll 4
            for (int j = 0; j < HID; ++j)
                s = fmaf(g_h1[p][j * BATCH + bg], W_out[a * HID + j], s);
            out[((size_t)(t - 1) * BATCH + bg) * ADIM + a] = tanh_fast(s);
        }

        grid_barrier(bar & 1); ++bar;        // h0(t) visible everywhere

        // ================= Phase B: layer 1 =================
        for (int idx = tid; idx < KB * BPC; idx += NTHR) {
            int bb = idx & 31;
            int k  = idx >> 5;
            float v = (k < HID) ? g_h0[p ^ 1][k * BATCH + b0 + bb]
                                : g_h1[p][(k - HID) * BATCH + b0 + bb];
            sIn[k * 33 + bb] = v;
        }
        __syncthreads();

        {
            float a0[4], a1[4];
            #pragma unroll
            for (int g = 0; g < 4; ++g) { a0[g] = bB0[g]; a1[g] = bB1[g]; }

            #pragma unroll 2
            for (int k4 = 0; k4 < KB; k4 += 4) {
                float x0 = sIn[(k4 + 0) * 33 + b];
                float x1 = sIn[(k4 + 1) * 33 + b];
                float x2 = sIn[(k4 + 2) * 33 + b];
                float x3 = sIn[(k4 + 3) * 33 + b];
                #pragma unroll
                for (int g = 0; g < 4; ++g) {
                    float4 w0 = *(const float4*)&sWB[(g * HPC + jl0) * KB + k4];
                    a0[g] = fmaf(w0.x, x0, fmaf(w0.y, x1, fmaf(w0.z, x2, fmaf(w0.w, x3, a0[g]))));
                    float4 w1 = *(const float4*)&sWB[(g * HPC + jl0 + 1) * KB + k4];
                    a1[g] = fmaf(w1.x, x0, fmaf(w1.y, x1, fmaf(w1.z, x2, fmaf(w1.w, x3, a1[g]))));
                }
            }
            {
                float iG = sigmoid_fast(a0[0]), fG = sigmoid_fast(a0[1]);
                float gG = tanh_fast(a0[2]),    oG = sigmoid_fast(a0[3]);
                c1a = fG * c1a + iG * gG;
                g_h1[p ^ 1][(j0 + jl0) * BATCH + b0 + b] = oG * tanh_fast(c1a);
            }
            {
                float iG = sigmoid_fast(a1[0]), fG = sigmoid_fast(a1[1]);
                float gG = tanh_fast(a1[2]),    oG = sigmoid_fast(a1[3]);
                c1b = fG * c1b + iG * gG;
                g_h1[p ^ 1][(j0 + jl0 + 1) * BATCH + b0 + b] = oG * tanh_fast(c1b);
            }
        }

        grid_barrier(bar & 1); ++bar;        // h1(t) visible everywhere
        p ^= 1;
    }

    // Final output head for t = T-1 (reads g_h1[p], guarded by last barrier)
    if (tid < 4 * ADIM) {
        int lb = tid / ADIM;
        int a  = tid - lb * ADIM;
        int bg = b0 + hs * 4 + lb;
        float s = b_out[a];
        #pragma unroll 4
        for (int j = 0; j < HID; ++j)
            s = fmaf(g_h1[p][j * BATCH + bg], W_out[a * HID + j], s);
        out[((size_t)(T_STEPS - 1) * BATCH + bg) * ADIM + a] = tanh_fast(s);
    }

    // Trailing barrier: makes total barrier count EVEN (1 + 1024 + 1 = 1026) so
    // both barrier slots are provably clean for the next graph replay.
    grid_barrier(bar & 1); ++bar;
}

extern "C" void kernel_launch(void* const* d_in, const int* in_sizes, int n_in,
                              void* d_out, int out_size)
{
    const float* x     = (const float*)d_in[0];
    const float* Wih0  = (const float*)d_in[1];
    const float* Whh0  = (const float*)d_in[2];
    const float* bih0  = (const float*)d_in[3];
    const float* bhh0  = (const float*)d_in[4];
    const float* Wih1  = (const float*)d_in[5];
    const float* Whh1  = (const float*)d_in[6];
    const float* bih1  = (const float*)d_in[7];
    const float* bhh1  = (const float*)d_in[8];
    const float* Wout  = (const float*)d_in[9];
    const float* bout  = (const float*)d_in[10];
    float* out = (float*)d_out;

    cudaFuncSetAttribute(lstm_persistent,
                         cudaFuncAttributeMaxDynamicSharedMemorySize, SMEM_BYTES);

    lstm_persistent<<<NCTA, NTHR, SMEM_BYTES>>>(
        x, Wih0, Whh0, bih0, bhh0, Wih1, Whh1, bih1, bhh1, Wout, bout, out);
}